// round 9
// baseline (speedup 1.0000x reference)
#include <cuda_runtime.h>

#define N_NODES 100000
#define N_EDGES 3200000
#define IN_DIM  256
#define HID     16
#define OUT_DIM 10
#define CAP     128          // per-node bucket capacity (deg ~ Binomial, mean 32, P(>128)~0)

#define REORDER_BLOCKS ((N_EDGES / 8 + 255) / 256)   // 1563
#define GEMM_BLOCKS    ((N_NODES + 255) / 256)       // 391

// ---- scratch -----------------------------------------------------------
__device__ float4 g_m1[N_NODES * 4];        // x@W1        [N,16]  (64B rows)
__device__ float4 g_m2[N_NODES * 4];        // layer2 out  [N,16]  (cols 10..15 = 0)
__device__ int    g_cursor[N_NODES];        // init n*CAP; end pointer after reorder
__device__ int    g_csr_src[N_NODES * CAP]; // bucketed src lists, entries = src<<6 (byte offset)

__device__ __forceinline__ void f4add(float4& a, const float4 b) {
    a.x += b.x; a.y += b.y; a.z += b.z; a.w += b.w;
}

// ---- cursor init -------------------------------------------------------
__global__ void k_cursor_init() {
    int i = blockIdx.x * blockDim.x + threadIdx.x;
    if (i < N_NODES) g_cursor[i] = i * CAP;
}

// ---- merged: reorder (blocks 0..REORDER_BLOCKS-1)  ||  gemm1 (rest) ----
#define KC 16
__global__ void __launch_bounds__(256) k_build_gemm(const int* __restrict__ ei,
                                                    const float* __restrict__ x,
                                                    const float* __restrict__ W1) {
    int tid = threadIdx.x;
    if (blockIdx.x < REORDER_BLOCKS) {
        // ---------------- reorder: 8 edges/thread, 8 independent atomic chains
        int t = blockIdx.x * 256 + tid;
        if (t >= N_EDGES / 8) return;
        const int4* s4 = (const int4*)ei;
        const int4* d4 = (const int4*)(ei + N_EDGES);
        int4 sa = s4[2 * t], sb = s4[2 * t + 1];
        int4 da = d4[2 * t], db = d4[2 * t + 1];
        int p0 = atomicAdd(&g_cursor[da.x], 1);
        int p1 = atomicAdd(&g_cursor[da.y], 1);
        int p2 = atomicAdd(&g_cursor[da.z], 1);
        int p3 = atomicAdd(&g_cursor[da.w], 1);
        int p4 = atomicAdd(&g_cursor[db.x], 1);
        int p5 = atomicAdd(&g_cursor[db.y], 1);
        int p6 = atomicAdd(&g_cursor[db.z], 1);
        int p7 = atomicAdd(&g_cursor[db.w], 1);
        g_csr_src[p0] = sa.x << 6; g_csr_src[p1] = sa.y << 6;
        g_csr_src[p2] = sa.z << 6; g_csr_src[p3] = sa.w << 6;
        g_csr_src[p4] = sb.x << 6; g_csr_src[p5] = sb.y << 6;
        g_csr_src[p6] = sb.z << 6; g_csr_src[p7] = sb.w << 6;
    } else {
        // ---------------- GEMM1: thread-per-row, smem-staged x, packed f32x2 FMA
        __shared__ float xs[256 * (KC + 1)];
        __shared__ float Ws[IN_DIM * HID];
        int bid = blockIdx.x - REORDER_BLOCKS;

        const float4* W14 = (const float4*)W1;
        float4* Ws4 = (float4*)Ws;
        for (int i = tid; i < IN_DIM * HID / 4; i += 256) Ws4[i] = W14[i];

        int row_base = bid * 256;
        int row = row_base + tid;
        const float4* x4 = (const float4*)x;

        unsigned long long acc[8];
#pragma unroll
        for (int p = 0; p < 8; p++) acc[p] = 0ull;

        int r = tid >> 2, c4 = tid & 3;
        for (int kc = 0; kc < IN_DIM / KC; kc++) {
            __syncthreads();
#pragma unroll
            for (int rr = 0; rr < 4; rr++) {
                int rl = r + rr * 64;
                int rg = row_base + rl;
                float4 v = (rg < N_NODES) ? x4[rg * 64 + kc * 4 + c4]
                                          : make_float4(0.f, 0.f, 0.f, 0.f);
                float* d = &xs[rl * (KC + 1) + c4 * 4];
                d[0] = v.x; d[1] = v.y; d[2] = v.z; d[3] = v.w;
            }
            __syncthreads();
            const float* xr = &xs[tid * (KC + 1)];
#pragma unroll
            for (int c = 0; c < KC; c++) {
                float xv = xr[c];
                unsigned long long xx;
                asm("mov.b64 %0, {%1,%1};" : "=l"(xx) : "f"(xv));
                const unsigned long long* wr =
                    (const unsigned long long*)&Ws[(kc * KC + c) * HID];
#pragma unroll
                for (int p = 0; p < 8; p++)
                    asm("fma.rn.f32x2 %0, %1, %2, %0;" : "+l"(acc[p]) : "l"(xx), "l"(wr[p]));
            }
        }
        if (row < N_NODES) {
            float o[16];
#pragma unroll
            for (int p = 0; p < 8; p++)
                asm("mov.b64 {%0,%1}, %2;" : "=f"(o[2 * p]), "=f"(o[2 * p + 1]) : "l"(acc[p]));
            g_m1[row * 4 + 0] = make_float4(o[0],  o[1],  o[2],  o[3]);
            g_m1[row * 4 + 1] = make_float4(o[4],  o[5],  o[6],  o[7]);
            g_m1[row * 4 + 2] = make_float4(o[8],  o[9],  o[10], o[11]);
            g_m1[row * 4 + 3] = make_float4(o[12], o[13], o[14], o[15]);
        }
    }
}

// ---- gather1 + layer2 fused --------------------------------------------
// warp per node; lane = (edge_slot = lane>>2, quarter = lane&3); csr holds src<<6
__global__ void __launch_bounds__(256) k_gather1_fused(const float* __restrict__ b1,
                                                       const float* __restrict__ W2) {
    __shared__ float W2s[HID * OUT_DIM];
    __shared__ float b1s[HID];
    int tid = threadIdx.x;
    for (int i = tid; i < HID * OUT_DIM; i += 256) W2s[i] = W2[i];
    if (tid < HID) b1s[tid] = b1[tid];
    __syncthreads();

    int n = blockIdx.x * 8 + (tid >> 5);
    if (n >= N_NODES) return;
    int lane = tid & 31;
    int start = n * CAP;
    int cnt = g_cursor[n] - start;
    int sub = lane >> 2;
    int qoff = (lane & 3) << 4;

    const char* m1b = (const char*)g_m1;
    const int* csr = g_csr_src + start;
    float4 acc = make_float4(0.f, 0.f, 0.f, 0.f);
    float4 acc1 = make_float4(0.f, 0.f, 0.f, 0.f);
    int i = sub;
    for (; i + 8 < cnt; i += 16) {
        int o0 = csr[i];
        int o1 = csr[i + 8];
        f4add(acc,  *(const float4*)(m1b + o0 + qoff));
        f4add(acc1, *(const float4*)(m1b + o1 + qoff));
    }
    if (i < cnt) f4add(acc, *(const float4*)(m1b + csr[i] + qoff));
    f4add(acc, acc1);
#pragma unroll
    for (int m = 16; m >= 4; m >>= 1) {
        acc.x += __shfl_xor_sync(0xffffffffu, acc.x, m);
        acc.y += __shfl_xor_sync(0xffffffffu, acc.y, m);
        acc.z += __shfl_xor_sync(0xffffffffu, acc.z, m);
        acc.w += __shfl_xor_sync(0xffffffffu, acc.w, m);
    }
    // lanes 0..3 hold quarter sums; broadcast h[16]
    float h[HID];
#pragma unroll
    for (int f = 0; f < HID; f++) {
        float comp = ((f & 3) == 0) ? acc.x : ((f & 3) == 1) ? acc.y
                   : ((f & 3) == 2) ? acc.z : acc.w;
        float v = __shfl_sync(0xffffffffu, comp, f >> 2) + b1s[f];
        h[f] = v > 0.f ? v : 0.f;
    }
    // m2 row = 16 floats (cols 10..15 zero)
    float* m2f = (float*)g_m2;
    if (lane < 16) {
        float o = 0.f;
        if (lane < OUT_DIM) {
#pragma unroll
            for (int f = 0; f < HID; f++) o += h[f] * W2s[f * OUT_DIM + lane];
        }
        m2f[n * 16 + lane] = o;
    }
}

// ---- gather2 + bias + output (identical access pattern to gather1) -----
__global__ void __launch_bounds__(256) k_gather2_out(float* __restrict__ out,
                                                     const float* __restrict__ b2) {
    __shared__ float b2s[OUT_DIM];
    int tid = threadIdx.x;
    if (tid < OUT_DIM) b2s[tid] = b2[tid];
    __syncthreads();

    int n = blockIdx.x * 8 + (tid >> 5);
    if (n >= N_NODES) return;
    int lane = tid & 31;
    int start = n * CAP;
    int cnt = g_cursor[n] - start;
    int sub = lane >> 2;
    int qoff = (lane & 3) << 4;

    const char* m2b = (const char*)g_m2;
    const int* csr = g_csr_src + start;
    float4 acc = make_float4(0.f, 0.f, 0.f, 0.f);
    float4 acc1 = make_float4(0.f, 0.f, 0.f, 0.f);
    int i = sub;
    for (; i + 8 < cnt; i += 16) {
        int o0 = csr[i];
        int o1 = csr[i + 8];
        f4add(acc,  *(const float4*)(m2b + o0 + qoff));
        f4add(acc1, *(const float4*)(m2b + o1 + qoff));
    }
    if (i < cnt) f4add(acc, *(const float4*)(m2b + csr[i] + qoff));
    f4add(acc, acc1);
#pragma unroll
    for (int m = 16; m >= 4; m >>= 1) {
        acc.x += __shfl_xor_sync(0xffffffffu, acc.x, m);
        acc.y += __shfl_xor_sync(0xffffffffu, acc.y, m);
        acc.z += __shfl_xor_sync(0xffffffffu, acc.z, m);
        acc.w += __shfl_xor_sync(0xffffffffu, acc.w, m);
    }
    // lane f (<10) needs component (f&3) of quarter (f>>2): 4 shfls + select
    int srcl = lane >> 2;
    float cx = __shfl_sync(0xffffffffu, acc.x, srcl);
    float cy = __shfl_sync(0xffffffffu, acc.y, srcl);
    float cz = __shfl_sync(0xffffffffu, acc.z, srcl);
    float cw = __shfl_sync(0xffffffffu, acc.w, srcl);
    if (lane < OUT_DIM) {
        int c = lane & 3;
        float v = (c == 0) ? cx : (c == 1) ? cy : (c == 2) ? cz : cw;
        out[n * OUT_DIM + lane] = v + b2s[lane];
    }
}

// ---- launch ------------------------------------------------------------
extern "C" void kernel_launch(void* const* d_in, const int* in_sizes, int n_in,
                              void* d_out, int out_size) {
    const float* x  = (const float*)d_in[0];
    const int*   ei = (const int*)d_in[1];   // int32 at runtime (JAX x64 off)
    const float* W1 = (const float*)d_in[2];
    const float* b1 = (const float*)d_in[3];
    const float* W2 = (const float*)d_in[4];
    const float* b2 = (const float*)d_in[5];
    float* out = (float*)d_out;

    k_cursor_init  <<<(N_NODES + 255) / 256, 256>>>();
    k_build_gemm   <<<REORDER_BLOCKS + GEMM_BLOCKS, 256>>>(ei, x, W1);
    k_gather1_fused<<<(N_NODES + 7) / 8, 256>>>(b1, W2);
    k_gather2_out  <<<(N_NODES + 7) / 8, 256>>>(out, b2);
}

// round 13
// speedup vs baseline: 1.0254x; 1.0254x over previous
#include <cuda_runtime.h>

#define N_NODES 100000
#define N_EDGES 3200000
#define IN_DIM  256
#define HID     16
#define OUT_DIM 10
#define CAP     128          // per-node bucket capacity (deg ~ Binomial, mean 32, P(>128)~0)

// ---- scratch -----------------------------------------------------------
__device__ float4 g_m1[N_NODES * 4];        // x@W1        [N,16]  (64B rows)
__device__ float4 g_m2[N_NODES * 4];        // layer2 out  [N,16]  (cols 10..15 = 0)
__device__ int    g_cursor[N_NODES];        // init n*CAP; end pointer after reorder
__device__ int    g_csr_src[N_NODES * CAP]; // bucketed src lists, entries = src<<6 (byte offset)

__device__ __forceinline__ void f4add(float4& a, const float4 b) {
    a.x += b.x; a.y += b.y; a.z += b.z; a.w += b.w;
}

// ---- cursor init -------------------------------------------------------
__global__ void k_cursor_init() {
    int i = blockIdx.x * blockDim.x + threadIdx.x;
    if (i < N_NODES) g_cursor[i] = i * CAP;
}

// ---- reorder: 8 edges/thread, 8 independent atomic chains (full occupancy)
__global__ void __launch_bounds__(256) k_reorder(const int* __restrict__ ei) {
    int t = blockIdx.x * 256 + threadIdx.x;
    if (t >= N_EDGES / 8) return;
    const int4* s4 = (const int4*)ei;
    const int4* d4 = (const int4*)(ei + N_EDGES);
    int4 sa = s4[2 * t], sb = s4[2 * t + 1];
    int4 da = d4[2 * t], db = d4[2 * t + 1];
    int p0 = atomicAdd(&g_cursor[da.x], 1);
    int p1 = atomicAdd(&g_cursor[da.y], 1);
    int p2 = atomicAdd(&g_cursor[da.z], 1);
    int p3 = atomicAdd(&g_cursor[da.w], 1);
    int p4 = atomicAdd(&g_cursor[db.x], 1);
    int p5 = atomicAdd(&g_cursor[db.y], 1);
    int p6 = atomicAdd(&g_cursor[db.z], 1);
    int p7 = atomicAdd(&g_cursor[db.w], 1);
    g_csr_src[p0] = sa.x << 6; g_csr_src[p1] = sa.y << 6;
    g_csr_src[p2] = sa.z << 6; g_csr_src[p3] = sa.w << 6;
    g_csr_src[p4] = sb.x << 6; g_csr_src[p5] = sb.y << 6;
    g_csr_src[p6] = sb.z << 6; g_csr_src[p7] = sb.w << 6;
}

// ---- GEMM1: m1 = x @ W1  (2 rows/thread: W-LDS amortized; packed f32x2 FMA)
#define KC 16
#define ROWS_PER_BLOCK 512
__global__ void __launch_bounds__(256) k_gemm1(const float* __restrict__ x,
                                               const float* __restrict__ W1) {
    __shared__ float xs[ROWS_PER_BLOCK * (KC + 1)];  // 34.8 KB, pad 17
    __shared__ float Ws[IN_DIM * HID];               // 16 KB, Ws[k*16+f]
    int tid = threadIdx.x;

    const float4* W14 = (const float4*)W1;
    float4* Ws4 = (float4*)Ws;
    for (int i = tid; i < IN_DIM * HID / 4; i += 256) Ws4[i] = W14[i];

    int row_base = blockIdx.x * ROWS_PER_BLOCK;
    int rowA = row_base + tid;            // rows tid and tid+256
    int rowB = rowA + 256;
    const float4* x4 = (const float4*)x;

    unsigned long long accA[8], accB[8];
#pragma unroll
    for (int p = 0; p < 8; p++) { accA[p] = 0ull; accB[p] = 0ull; }

    int r = tid >> 2, c4 = tid & 3;       // staging: 64 rows x 4 float4 per pass
    for (int kc = 0; kc < IN_DIM / KC; kc++) {
        __syncthreads();
#pragma unroll
        for (int rr = 0; rr < 8; rr++) {
            int rl = r + rr * 64;
            int rg = row_base + rl;
            float4 v = (rg < N_NODES) ? x4[rg * 64 + kc * 4 + c4]
                                      : make_float4(0.f, 0.f, 0.f, 0.f);
            float* d = &xs[rl * (KC + 1) + c4 * 4];
            d[0] = v.x; d[1] = v.y; d[2] = v.z; d[3] = v.w;
        }
        __syncthreads();
        const float* xrA = &xs[tid * (KC + 1)];
        const float* xrB = &xs[(tid + 256) * (KC + 1)];
#pragma unroll
        for (int c = 0; c < KC; c++) {
            float xa = xrA[c], xb = xrB[c];
            unsigned long long xxA, xxB;
            asm("mov.b64 %0, {%1,%1};" : "=l"(xxA) : "f"(xa));
            asm("mov.b64 %0, {%1,%1};" : "=l"(xxB) : "f"(xb));
            const unsigned long long* wr =
                (const unsigned long long*)&Ws[(kc * KC + c) * HID];
#pragma unroll
            for (int p = 0; p < 8; p++) {
                unsigned long long w = wr[p];   // one broadcast LDS.64, two rows
                asm("fma.rn.f32x2 %0, %1, %2, %0;" : "+l"(accA[p]) : "l"(xxA), "l"(w));
                asm("fma.rn.f32x2 %0, %1, %2, %0;" : "+l"(accB[p]) : "l"(xxB), "l"(w));
            }
        }
    }
    if (rowA < N_NODES) {
        float o[16];
#pragma unroll
        for (int p = 0; p < 8; p++)
            asm("mov.b64 {%0,%1}, %2;" : "=f"(o[2 * p]), "=f"(o[2 * p + 1]) : "l"(accA[p]));
        g_m1[rowA * 4 + 0] = make_float4(o[0],  o[1],  o[2],  o[3]);
        g_m1[rowA * 4 + 1] = make_float4(o[4],  o[5],  o[6],  o[7]);
        g_m1[rowA * 4 + 2] = make_float4(o[8],  o[9],  o[10], o[11]);
        g_m1[rowA * 4 + 3] = make_float4(o[12], o[13], o[14], o[15]);
    }
    if (rowB < N_NODES) {
        float o[16];
#pragma unroll
        for (int p = 0; p < 8; p++)
            asm("mov.b64 {%0,%1}, %2;" : "=f"(o[2 * p]), "=f"(o[2 * p + 1]) : "l"(accB[p]));
        g_m1[rowB * 4 + 0] = make_float4(o[0],  o[1],  o[2],  o[3]);
        g_m1[rowB * 4 + 1] = make_float4(o[4],  o[5],  o[6],  o[7]);
        g_m1[rowB * 4 + 2] = make_float4(o[8],  o[9],  o[10], o[11]);
        g_m1[rowB * 4 + 3] = make_float4(o[12], o[13], o[14], o[15]);
    }
}

// ---- gather1 + layer2 fused --------------------------------------------
// warp per node; lane = (edge_slot = lane>>2, quarter = lane&3); csr holds src<<6
__global__ void __launch_bounds__(256) k_gather1_fused(const float* __restrict__ b1,
                                                       const float* __restrict__ W2) {
    __shared__ float W2s[HID * OUT_DIM];
    __shared__ float b1s[HID];
    int tid = threadIdx.x;
    for (int i = tid; i < HID * OUT_DIM; i += 256) W2s[i] = W2[i];
    if (tid < HID) b1s[tid] = b1[tid];
    __syncthreads();

    int n = blockIdx.x * 8 + (tid >> 5);
    if (n >= N_NODES) return;
    int lane = tid & 31;
    int start = n * CAP;
    int cnt = g_cursor[n] - start;
    int sub = lane >> 2;
    int qoff = (lane & 3) << 4;

    const char* m1b = (const char*)g_m1;
    const int* csr = g_csr_src + start;
    float4 acc = make_float4(0.f, 0.f, 0.f, 0.f);
    float4 acc1 = make_float4(0.f, 0.f, 0.f, 0.f);
    int i = sub;
    for (; i + 8 < cnt; i += 16) {
        int o0 = csr[i];
        int o1 = csr[i + 8];
        f4add(acc,  *(const float4*)(m1b + o0 + qoff));
        f4add(acc1, *(const float4*)(m1b + o1 + qoff));
    }
    if (i < cnt) f4add(acc, *(const float4*)(m1b + csr[i] + qoff));
    f4add(acc, acc1);
#pragma unroll
    for (int m = 16; m >= 4; m >>= 1) {
        acc.x += __shfl_xor_sync(0xffffffffu, acc.x, m);
        acc.y += __shfl_xor_sync(0xffffffffu, acc.y, m);
        acc.z += __shfl_xor_sync(0xffffffffu, acc.z, m);
        acc.w += __shfl_xor_sync(0xffffffffu, acc.w, m);
    }
    // lanes 0..3 hold quarter sums; broadcast h[16]
    float h[HID];
#pragma unroll
    for (int f = 0; f < HID; f++) {
        float comp = ((f & 3) == 0) ? acc.x : ((f & 3) == 1) ? acc.y
                   : ((f & 3) == 2) ? acc.z : acc.w;
        float v = __shfl_sync(0xffffffffu, comp, f >> 2) + b1s[f];
        h[f] = v > 0.f ? v : 0.f;
    }
    // m2 row = 16 floats (cols 10..15 zero)
    float* m2f = (float*)g_m2;
    if (lane < 16) {
        float o = 0.f;
        if (lane < OUT_DIM) {
#pragma unroll
            for (int f = 0; f < HID; f++) o += h[f] * W2s[f * OUT_DIM + lane];
        }
        m2f[n * 16 + lane] = o;
    }
}

// ---- gather2 + bias + output -------------------------------------------
__global__ void __launch_bounds__(256) k_gather2_out(float* __restrict__ out,
                                                     const float* __restrict__ b2) {
    __shared__ float b2s[OUT_DIM];
    int tid = threadIdx.x;
    if (tid < OUT_DIM) b2s[tid] = b2[tid];
    __syncthreads();

    int n = blockIdx.x * 8 + (tid >> 5);
    if (n >= N_NODES) return;
    int lane = tid & 31;
    int start = n * CAP;
    int cnt = g_cursor[n] - start;
    int sub = lane >> 2;
    int qoff = (lane & 3) << 4;

    const char* m2b = (const char*)g_m2;
    const int* csr = g_csr_src + start;
    float4 acc = make_float4(0.f, 0.f, 0.f, 0.f);
    float4 acc1 = make_float4(0.f, 0.f, 0.f, 0.f);
    int i = sub;
    for (; i + 8 < cnt; i += 16) {
        int o0 = csr[i];
        int o1 = csr[i + 8];
        f4add(acc,  *(const float4*)(m2b + o0 + qoff));
        f4add(acc1, *(const float4*)(m2b + o1 + qoff));
    }
    if (i < cnt) f4add(acc, *(const float4*)(m2b + csr[i] + qoff));
    f4add(acc, acc1);
#pragma unroll
    for (int m = 16; m >= 4; m >>= 1) {
        acc.x += __shfl_xor_sync(0xffffffffu, acc.x, m);
        acc.y += __shfl_xor_sync(0xffffffffu, acc.y, m);
        acc.z += __shfl_xor_sync(0xffffffffu, acc.z, m);
        acc.w += __shfl_xor_sync(0xffffffffu, acc.w, m);
    }
    int srcl = lane >> 2;
    float cx = __shfl_sync(0xffffffffu, acc.x, srcl);
    float cy = __shfl_sync(0xffffffffu, acc.y, srcl);
    float cz = __shfl_sync(0xffffffffu, acc.z, srcl);
    float cw = __shfl_sync(0xffffffffu, acc.w, srcl);
    if (lane < OUT_DIM) {
        int c = lane & 3;
        float v = (c == 0) ? cx : (c == 1) ? cy : (c == 2) ? cz : cw;
        out[n * OUT_DIM + lane] = v + b2s[lane];
    }
}

// ---- launch ------------------------------------------------------------
extern "C" void kernel_launch(void* const* d_in, const int* in_sizes, int n_in,
                              void* d_out, int out_size) {
    const float* x  = (const float*)d_in[0];
    const int*   ei = (const int*)d_in[1];   // int32 at runtime (JAX x64 off)
    const float* W1 = (const float*)d_in[2];
    const float* b1 = (const float*)d_in[3];
    const float* W2 = (const float*)d_in[4];
    const float* b2 = (const float*)d_in[5];
    float* out = (float*)d_out;

    k_cursor_init  <<<(N_NODES + 255) / 256, 256>>>();
    k_reorder      <<<(N_EDGES / 8 + 255) / 256, 256>>>(ei);
    k_gemm1        <<<(N_NODES + ROWS_PER_BLOCK - 1) / ROWS_PER_BLOCK, 256>>>(x, W1);
    k_gather1_fused<<<(N_NODES + 7) / 8, 256>>>(b1, W2);
    k_gather2_out  <<<(N_NODES + 7) / 8, 256>>>(out, b2);
}